// round 8
// baseline (speedup 1.0000x reference)
#include <cuda_runtime.h>
#include <math.h>

#define N_NODES 50000
#define N_EDGES 800000
#define D_IN    128
#define D_HID   128
#define D_OUT   256

// ---------------- scratch (static device globals — no allocations) ----------
__device__ float g_h[(size_t)N_NODES * D_HID];      // layer-1 output (normalized)
__device__ float g_agg[(size_t)N_NODES * D_IN];     // mean-aggregated features
__device__ int   g_deg[N_NODES];
__device__ int   g_row[N_NODES + 1];
__device__ int   g_cursor[N_NODES];
__device__ int   g_csr[N_EDGES];                    // src indices grouped by dst

// ---------------- CSR build ----------------
__global__ void k_zero_deg() {
    int i = blockIdx.x * blockDim.x + threadIdx.x;
    if (i < N_NODES) g_deg[i] = 0;
}

__global__ void k_count(const int* __restrict__ dst) {
    for (int e = blockIdx.x * blockDim.x + threadIdx.x; e < N_EDGES;
         e += gridDim.x * blockDim.x)
        atomicAdd(&g_deg[dst[e]], 1);
}

// single-block exclusive scan of degrees -> row offsets + cursor copy
__global__ void k_scan() {
    __shared__ int part[1024];
    const int tid = threadIdx.x;
    const int chunk = (N_NODES + 1023) / 1024;   // 49
    int base = tid * chunk;
    int s = 0;
    for (int j = 0; j < chunk; j++) {
        int idx = base + j;
        if (idx < N_NODES) s += g_deg[idx];
    }
    part[tid] = s;
    __syncthreads();
    for (int off = 1; off < 1024; off <<= 1) {
        int v = (tid >= off) ? part[tid - off] : 0;
        __syncthreads();
        part[tid] += v;
        __syncthreads();
    }
    int run = (tid > 0) ? part[tid - 1] : 0;
    for (int j = 0; j < chunk; j++) {
        int idx = base + j;
        if (idx < N_NODES) {
            g_row[idx] = run;
            g_cursor[idx] = run;
            run += g_deg[idx];
        }
    }
    if (tid == 1023) g_row[N_NODES] = part[1023];
}

__global__ void k_fill(const int* __restrict__ src, const int* __restrict__ dst) {
    for (int e = blockIdx.x * blockDim.x + threadIdx.x; e < N_EDGES;
         e += gridDim.x * blockDim.x) {
        int d = dst[e];
        int p = atomicAdd(&g_cursor[d], 1);
        g_csr[p] = src[e];
    }
}

// ---------------- mean aggregation: one warp per destination node -----------
// feat rows are 128 floats; each lane owns 4 contiguous floats. 4-deep unroll
// keeps >=4 independent L2 loads in flight per warp (L2 hit ~234cyc).
template <bool USE_H>
__global__ void __launch_bounds__(256) k_agg(const float* __restrict__ xin) {
    const float* __restrict__ feat = USE_H ? (const float*)g_h : xin;
    int warp = threadIdx.x >> 5;
    int lane = threadIdx.x & 31;
    int node = blockIdx.x * 8 + warp;
    if (node >= N_NODES) return;
    int s = g_row[node];
    int e = g_row[node + 1];

    float4 a0 = make_float4(0.f, 0.f, 0.f, 0.f);
    float4 a1 = make_float4(0.f, 0.f, 0.f, 0.f);
    float4 a2 = make_float4(0.f, 0.f, 0.f, 0.f);
    float4 a3 = make_float4(0.f, 0.f, 0.f, 0.f);
    int i = s;
    for (; i + 3 < e; i += 4) {
        int u0 = g_csr[i];
        int u1 = g_csr[i + 1];
        int u2 = g_csr[i + 2];
        int u3 = g_csr[i + 3];
        float4 v0 = *(const float4*)(feat + (size_t)u0 * 128 + lane * 4);
        float4 v1 = *(const float4*)(feat + (size_t)u1 * 128 + lane * 4);
        float4 v2 = *(const float4*)(feat + (size_t)u2 * 128 + lane * 4);
        float4 v3 = *(const float4*)(feat + (size_t)u3 * 128 + lane * 4);
        a0.x += v0.x; a0.y += v0.y; a0.z += v0.z; a0.w += v0.w;
        a1.x += v1.x; a1.y += v1.y; a1.z += v1.z; a1.w += v1.w;
        a2.x += v2.x; a2.y += v2.y; a2.z += v2.z; a2.w += v2.w;
        a3.x += v3.x; a3.y += v3.y; a3.z += v3.z; a3.w += v3.w;
    }
    for (; i < e; i++) {
        int u0 = g_csr[i];
        float4 v0 = *(const float4*)(feat + (size_t)u0 * 128 + lane * 4);
        a0.x += v0.x; a0.y += v0.y; a0.z += v0.z; a0.w += v0.w;
    }
    float invd = (e > s) ? 1.f / (float)(e - s) : 0.f;
    float4 r;
    r.x = (a0.x + a1.x + a2.x + a3.x) * invd;
    r.y = (a0.y + a1.y + a2.y + a3.y) * invd;
    r.z = (a0.z + a1.z + a2.z + a3.z) * invd;
    r.w = (a0.w + a1.w + a2.w + a3.w) * invd;
    *(float4*)(g_agg + (size_t)node * 128 + lane * 4) = r;
}

// ---------------- layer 1 GEMM: h = l2norm(sigmoid(agg@Wl + x@Wr + b)) ------
// Tile 64 rows x 128 cols (full width), K = 2*128 over (agg,Wl) then (x,Wr).
// 256 threads, micro tile 8x4. Warp tr owns rows tr*8..tr*8+7; lane tc owns
// cols tc*4..tc*4+3 => per-row reductions are warp butterflies.
#define BM 64
#define BK 32
#define ASTRIDE 68   // padded: keeps 16B alignment, breaks STS conflicts

__global__ void __launch_bounds__(256) k_gemm1(const float* __restrict__ x,
                                               const float* __restrict__ Wl,
                                               const float* __restrict__ Wr,
                                               const float* __restrict__ bias) {
    __shared__ float As[BK * ASTRIDE];
    __shared__ float Bs[BK * 128];
    const int tid = threadIdx.x;
    const int tr = tid >> 5;
    const int tc = tid & 31;
    const int m0 = blockIdx.x * BM;

    float acc[8][4];
#pragma unroll
    for (int i = 0; i < 8; i++)
#pragma unroll
        for (int j = 0; j < 4; j++) acc[i][j] = 0.f;

#pragma unroll 1
    for (int kc = 0; kc < 8; kc++) {
        const float* A = (kc < 4) ? (const float*)g_agg : x;
        const float* W = (kc < 4) ? Wl : Wr;
        const int k0 = (kc & 3) * BK;

        // A tile (transposed into smem): 64 rows x 32 k
#pragma unroll
        for (int t = 0; t < 2; t++) {
            int idx = tid * 2 + t;          // 0..511 float4s
            int row = idx >> 3;             // 0..63
            int c4  = idx & 7;              // 0..7
            int gm  = m0 + row;
            float4 v = make_float4(0.f, 0.f, 0.f, 0.f);
            if (gm < N_NODES)
                v = *(const float4*)(A + (size_t)gm * 128 + k0 + c4 * 4);
            As[(c4 * 4 + 0) * ASTRIDE + row] = v.x;
            As[(c4 * 4 + 1) * ASTRIDE + row] = v.y;
            As[(c4 * 4 + 2) * ASTRIDE + row] = v.z;
            As[(c4 * 4 + 3) * ASTRIDE + row] = v.w;
        }
        // B tile: rows k0..k0+31 of W[128][128]
#pragma unroll
        for (int t = 0; t < 4; t++) {
            int idx = tid + t * 256;        // 0..1023 float4s
            int row = idx >> 5;             // 0..31
            int c4  = idx & 31;             // 0..31
            *(float4*)&Bs[row * 128 + c4 * 4] =
                *(const float4*)(W + (size_t)(k0 + row) * 128 + c4 * 4);
        }
        __syncthreads();

#pragma unroll
        for (int k = 0; k < BK; k++) {
            float4 a0 = *(const float4*)&As[k * ASTRIDE + tr * 8];
            float4 a1 = *(const float4*)&As[k * ASTRIDE + tr * 8 + 4];
            float4 bq = *(const float4*)&Bs[k * 128 + tc * 4];
            float av[8] = {a0.x, a0.y, a0.z, a0.w, a1.x, a1.y, a1.z, a1.w};
            float bv[4] = {bq.x, bq.y, bq.z, bq.w};
#pragma unroll
            for (int i = 0; i < 8; i++)
#pragma unroll
                for (int j = 0; j < 4; j++) acc[i][j] += av[i] * bv[j];
        }
        __syncthreads();
    }

    // epilogue: bias + sigmoid + L2-normalize (row = warp)
    float4 bb = *(const float4*)(bias + tc * 4);
    float bv4[4] = {bb.x, bb.y, bb.z, bb.w};
#pragma unroll
    for (int i = 0; i < 8; i++) {
        int row = m0 + tr * 8 + i;
        float s[4];
        float sq = 0.f;
#pragma unroll
        for (int j = 0; j < 4; j++) {
            float v = acc[i][j] + bv4[j];
            float sg = 1.f / (1.f + __expf(-v));
            s[j] = sg;
            sq += sg * sg;
        }
#pragma unroll
        for (int off = 16; off; off >>= 1)
            sq += __shfl_xor_sync(0xffffffffu, sq, off);
        float inv = 1.f / fmaxf(sqrtf(sq), 1e-12f);
        if (row < N_NODES) {
            float4 o;
            o.x = s[0] * inv; o.y = s[1] * inv;
            o.z = s[2] * inv; o.w = s[3] * inv;
            *(float4*)(g_h + (size_t)row * 128 + tc * 4) = o;
        }
    }
}

// ---------------- layer 2 GEMM: out = log_softmax(l2norm(sigmoid(...))) ----
// Tile 64 x 256 (full width), micro tile 8x8. Lane tc owns cols tc*8..tc*8+7.
__global__ void __launch_bounds__(256) k_gemm2(const float* __restrict__ Wl,
                                               const float* __restrict__ Wr,
                                               const float* __restrict__ bias,
                                               float* __restrict__ out) {
    __shared__ float As[BK * ASTRIDE];
    __shared__ float Bs[BK * 256];
    const int tid = threadIdx.x;
    const int tr = tid >> 5;
    const int tc = tid & 31;
    const int m0 = blockIdx.x * BM;

    float acc[8][8];
#pragma unroll
    for (int i = 0; i < 8; i++)
#pragma unroll
        for (int j = 0; j < 8; j++) acc[i][j] = 0.f;

#pragma unroll 1
    for (int kc = 0; kc < 8; kc++) {
        const float* A = (kc < 4) ? (const float*)g_agg : (const float*)g_h;
        const float* W = (kc < 4) ? Wl : Wr;
        const int k0 = (kc & 3) * BK;

#pragma unroll
        for (int t = 0; t < 2; t++) {
            int idx = tid * 2 + t;
            int row = idx >> 3;
            int c4  = idx & 7;
            int gm  = m0 + row;
            float4 v = make_float4(0.f, 0.f, 0.f, 0.f);
            if (gm < N_NODES)
                v = *(const float4*)(A + (size_t)gm * 128 + k0 + c4 * 4);
            As[(c4 * 4 + 0) * ASTRIDE + row] = v.x;
            As[(c4 * 4 + 1) * ASTRIDE + row] = v.y;
            As[(c4 * 4 + 2) * ASTRIDE + row] = v.z;
            As[(c4 * 4 + 3) * ASTRIDE + row] = v.w;
        }
        // B tile: rows k0..k0+31 of W[128][256]  (2048 float4s, 8/thread)
#pragma unroll
        for (int t = 0; t < 8; t++) {
            int idx = tid + t * 256;        // 0..2047
            int row = idx >> 6;             // 0..31 (64 f4 per row)
            int c4  = idx & 63;
            *(float4*)&Bs[row * 256 + c4 * 4] =
                *(const float4*)(W + (size_t)(k0 + row) * 256 + c4 * 4);
        }
        __syncthreads();

#pragma unroll
        for (int k = 0; k < BK; k++) {
            float4 a0 = *(const float4*)&As[k * ASTRIDE + tr * 8];
            float4 a1 = *(const float4*)&As[k * ASTRIDE + tr * 8 + 4];
            float4 b0 = *(const float4*)&Bs[k * 256 + tc * 8];
            float4 b1 = *(const float4*)&Bs[k * 256 + tc * 8 + 4];
            float av[8] = {a0.x, a0.y, a0.z, a0.w, a1.x, a1.y, a1.z, a1.w};
            float bv[8] = {b0.x, b0.y, b0.z, b0.w, b1.x, b1.y, b1.z, b1.w};
#pragma unroll
            for (int i = 0; i < 8; i++)
#pragma unroll
                for (int j = 0; j < 8; j++) acc[i][j] += av[i] * bv[j];
        }
        __syncthreads();
    }

    // epilogue: bias + sigmoid + L2-normalize + log_softmax (row = warp)
    float4 b0 = *(const float4*)(bias + tc * 8);
    float4 b1 = *(const float4*)(bias + tc * 8 + 4);
    float bv8[8] = {b0.x, b0.y, b0.z, b0.w, b1.x, b1.y, b1.z, b1.w};
#pragma unroll
    for (int i = 0; i < 8; i++) {
        int row = m0 + tr * 8 + i;
        float sq = 0.f;
#pragma unroll
        for (int j = 0; j < 8; j++) {
            float v = acc[i][j] + bv8[j];
            float sg = 1.f / (1.f + __expf(-v));
            acc[i][j] = sg;
            sq += sg * sg;
        }
#pragma unroll
        for (int off = 16; off; off >>= 1)
            sq += __shfl_xor_sync(0xffffffffu, sq, off);
        float inv = 1.f / fmaxf(sqrtf(sq), 1e-12f);

        float mx = -1e30f;
#pragma unroll
        for (int j = 0; j < 8; j++) {
            float z = acc[i][j] * inv;
            acc[i][j] = z;
            mx = fmaxf(mx, z);
        }
#pragma unroll
        for (int off = 16; off; off >>= 1)
            mx = fmaxf(mx, __shfl_xor_sync(0xffffffffu, mx, off));

        float se = 0.f;
#pragma unroll
        for (int j = 0; j < 8; j++) se += __expf(acc[i][j] - mx);
#pragma unroll
        for (int off = 16; off; off >>= 1)
            se += __shfl_xor_sync(0xffffffffu, se, off);
        float lse = mx + __logf(se);

        if (row < N_NODES) {
            float4 o0, o1;
            o0.x = acc[i][0] - lse; o0.y = acc[i][1] - lse;
            o0.z = acc[i][2] - lse; o0.w = acc[i][3] - lse;
            o1.x = acc[i][4] - lse; o1.y = acc[i][5] - lse;
            o1.z = acc[i][6] - lse; o1.w = acc[i][7] - lse;
            *(float4*)(out + (size_t)row * 256 + tc * 8)     = o0;
            *(float4*)(out + (size_t)row * 256 + tc * 8 + 4) = o1;
        }
    }
}

// ---------------- launch -----------------
extern "C" void kernel_launch(void* const* d_in, const int* in_sizes, int n_in,
                              void* d_out, int out_size) {
    const float* x   = (const float*)d_in[0];
    const int*   ei  = (const int*)d_in[1];
    const float* W1l = (const float*)d_in[2];
    const float* W1r = (const float*)d_in[3];
    const float* b1  = (const float*)d_in[4];
    const float* W2l = (const float*)d_in[5];
    const float* W2r = (const float*)d_in[6];
    const float* b2  = (const float*)d_in[7];
    float* out = (float*)d_out;

    const int* src = ei;            // edge_index[0]
    const int* dst = ei + N_EDGES;  // edge_index[1]

    // CSR by destination
    k_zero_deg<<<(N_NODES + 255) / 256, 256>>>();
    k_count<<<592, 256>>>(dst);
    k_scan<<<1, 1024>>>();
    k_fill<<<592, 256>>>(src, dst);

    // layer 1
    k_agg<false><<<(N_NODES + 7) / 8, 256>>>(x);
    k_gemm1<<<(N_NODES + BM - 1) / BM, 256>>>(x, W1l, W1r, b1);

    // layer 2
    k_agg<true><<<(N_NODES + 7) / 8, 256>>>(x);
    k_gemm2<<<(N_NODES + BM - 1) / BM, 256>>>(W2l, W2r, b2, out);
}

// round 10
// speedup vs baseline: 1.0516x; 1.0516x over previous
#include <cuda_runtime.h>
#include <math.h>
#include <stdint.h>

#define N_NODES 50000
#define N_EDGES 800000
#define D_IN    128
#define D_HID   128
#define D_OUT   256

// ---------------- scratch (static device globals — no allocations) ----------
__device__ float g_h[(size_t)N_NODES * D_HID];      // layer-1 output (normalized)
__device__ float g_agg[(size_t)N_NODES * D_IN];     // mean-aggregated features
__device__ int   g_deg[N_NODES];
__device__ int   g_row[N_NODES + 1];
__device__ int   g_cursor[N_NODES];
__device__ int   g_csr[N_EDGES];                    // src indices grouped by dst

// ---------------- packed f32x2 helpers (FFMA2 — 2 FMAs per issue) -----------
typedef unsigned long long u64;

__device__ __forceinline__ void fma2(u64& acc, u64 a, u64 b) {
    asm("fma.rn.f32x2 %0, %1, %2, %0;" : "+l"(acc) : "l"(a), "l"(b));
}
__device__ __forceinline__ u64 splat2(float x) {
    u64 r;
    asm("mov.b64 %0, {%1, %1};" : "=l"(r) : "f"(x));
    return r;
}
__device__ __forceinline__ float2 unpack2(u64 v) {
    float2 r;
    asm("mov.b64 {%0, %1}, %2;" : "=f"(r.x), "=f"(r.y) : "l"(v));
    return r;
}

// ---------------- CSR build ----------------
__global__ void k_zero_deg() {
    int i = blockIdx.x * blockDim.x + threadIdx.x;
    if (i < N_NODES) g_deg[i] = 0;
}

__global__ void k_count(const int* __restrict__ dst) {
    for (int e = blockIdx.x * blockDim.x + threadIdx.x; e < N_EDGES;
         e += gridDim.x * blockDim.x)
        atomicAdd(&g_deg[dst[e]], 1);
}

// single-block exclusive scan of degrees -> row offsets + cursor copy
__global__ void k_scan() {
    __shared__ int part[1024];
    const int tid = threadIdx.x;
    const int chunk = (N_NODES + 1023) / 1024;   // 49
    int base = tid * chunk;
    int s = 0;
    for (int j = 0; j < chunk; j++) {
        int idx = base + j;
        if (idx < N_NODES) s += g_deg[idx];
    }
    part[tid] = s;
    __syncthreads();
    for (int off = 1; off < 1024; off <<= 1) {
        int v = (tid >= off) ? part[tid - off] : 0;
        __syncthreads();
        part[tid] += v;
        __syncthreads();
    }
    int run = (tid > 0) ? part[tid - 1] : 0;
    for (int j = 0; j < chunk; j++) {
        int idx = base + j;
        if (idx < N_NODES) {
            g_row[idx] = run;
            g_cursor[idx] = run;
            run += g_deg[idx];
        }
    }
    if (tid == 1023) g_row[N_NODES] = part[1023];
}

__global__ void k_fill(const int* __restrict__ src, const int* __restrict__ dst) {
    for (int e = blockIdx.x * blockDim.x + threadIdx.x; e < N_EDGES;
         e += gridDim.x * blockDim.x) {
        int d = dst[e];
        int p = atomicAdd(&g_cursor[d], 1);
        g_csr[p] = src[e];
    }
}

// ---------------- mean aggregation: one warp per destination node -----------
template <bool USE_H>
__global__ void __launch_bounds__(256) k_agg(const float* __restrict__ xin) {
    const float* __restrict__ feat = USE_H ? (const float*)g_h : xin;
    int warp = threadIdx.x >> 5;
    int lane = threadIdx.x & 31;
    int node = blockIdx.x * 8 + warp;
    if (node >= N_NODES) return;
    int s = g_row[node];
    int e = g_row[node + 1];

    float4 a0 = make_float4(0.f, 0.f, 0.f, 0.f);
    float4 a1 = make_float4(0.f, 0.f, 0.f, 0.f);
    float4 a2 = make_float4(0.f, 0.f, 0.f, 0.f);
    float4 a3 = make_float4(0.f, 0.f, 0.f, 0.f);
    int i = s;
    for (; i + 3 < e; i += 4) {
        int u0 = g_csr[i];
        int u1 = g_csr[i + 1];
        int u2 = g_csr[i + 2];
        int u3 = g_csr[i + 3];
        float4 v0 = *(const float4*)(feat + (size_t)u0 * 128 + lane * 4);
        float4 v1 = *(const float4*)(feat + (size_t)u1 * 128 + lane * 4);
        float4 v2 = *(const float4*)(feat + (size_t)u2 * 128 + lane * 4);
        float4 v3 = *(const float4*)(feat + (size_t)u3 * 128 + lane * 4);
        a0.x += v0.x; a0.y += v0.y; a0.z += v0.z; a0.w += v0.w;
        a1.x += v1.x; a1.y += v1.y; a1.z += v1.z; a1.w += v1.w;
        a2.x += v2.x; a2.y += v2.y; a2.z += v2.z; a2.w += v2.w;
        a3.x += v3.x; a3.y += v3.y; a3.z += v3.z; a3.w += v3.w;
    }
    for (; i < e; i++) {
        int u0 = g_csr[i];
        float4 v0 = *(const float4*)(feat + (size_t)u0 * 128 + lane * 4);
        a0.x += v0.x; a0.y += v0.y; a0.z += v0.z; a0.w += v0.w;
    }
    float invd = (e > s) ? 1.f / (float)(e - s) : 0.f;
    float4 r;
    r.x = (a0.x + a1.x + a2.x + a3.x) * invd;
    r.y = (a0.y + a1.y + a2.y + a3.y) * invd;
    r.z = (a0.z + a1.z + a2.z + a3.z) * invd;
    r.w = (a0.w + a1.w + a2.w + a3.w) * invd;
    *(float4*)(g_agg + (size_t)node * 128 + lane * 4) = r;
}

// ---------------- layer 1 GEMM (FFMA2): h = l2norm(sigmoid(...)) ------------
// Tile 64 rows x 128 cols, K = 2*128. 256 threads. Warp tr owns rows
// tr*8..tr*8+7 packed as 4 row-pairs (f32x2); lane tc owns cols tc*4..tc*4+3.
#define BM 64
#define BK 32
#define ASTRIDE 68   // 68 floats = 272 B: 16B-aligned rows, staggered banks

__global__ void __launch_bounds__(256) k_gemm1(const float* __restrict__ x,
                                               const float* __restrict__ Wl,
                                               const float* __restrict__ Wr,
                                               const float* __restrict__ bias) {
    __shared__ float As[BK * ASTRIDE];
    __shared__ float Bs[BK * 128];
    const int tid = threadIdx.x;
    const int tr = tid >> 5;
    const int tc = tid & 31;
    const int m0 = blockIdx.x * BM;

    u64 acc[4][4];   // [row-pair][col]
#pragma unroll
    for (int p = 0; p < 4; p++)
#pragma unroll
        for (int j = 0; j < 4; j++) acc[p][j] = 0ULL;

#pragma unroll 1
    for (int kc = 0; kc < 8; kc++) {
        const float* A = (kc < 4) ? (const float*)g_agg : x;
        const float* W = (kc < 4) ? Wl : Wr;
        const int k0 = (kc & 3) * BK;

        // A tile (transposed into smem): 64 rows x 32 k
#pragma unroll
        for (int t = 0; t < 2; t++) {
            int idx = tid * 2 + t;          // 0..511 float4s
            int row = idx >> 3;             // 0..63
            int c4  = idx & 7;              // 0..7
            int gm  = m0 + row;
            float4 v = make_float4(0.f, 0.f, 0.f, 0.f);
            if (gm < N_NODES)
                v = *(const float4*)(A + (size_t)gm * 128 + k0 + c4 * 4);
            As[(c4 * 4 + 0) * ASTRIDE + row] = v.x;
            As[(c4 * 4 + 1) * ASTRIDE + row] = v.y;
            As[(c4 * 4 + 2) * ASTRIDE + row] = v.z;
            As[(c4 * 4 + 3) * ASTRIDE + row] = v.w;
        }
        // B tile: rows k0..k0+31 of W[128][128]
#pragma unroll
        for (int t = 0; t < 4; t++) {
            int idx = tid + t * 256;        // 0..1023 float4s
            int row = idx >> 5;             // 0..31
            int c4  = idx & 31;             // 0..31
            *(float4*)&Bs[row * 128 + c4 * 4] =
                *(const float4*)(W + (size_t)(k0 + row) * 128 + c4 * 4);
        }
        __syncthreads();

#pragma unroll
        for (int k = 0; k < BK; k++) {
            // rows tr*8..tr*8+7 as 4 packed pairs (natural adjacency in As)
            ulonglong2 a01 = *(const ulonglong2*)&As[k * ASTRIDE + tr * 8];
            ulonglong2 a23 = *(const ulonglong2*)&As[k * ASTRIDE + tr * 8 + 4];
            float4 bq = *(const float4*)&Bs[k * 128 + tc * 4];
            u64 ar[4] = {a01.x, a01.y, a23.x, a23.y};
            u64 bs[4] = {splat2(bq.x), splat2(bq.y), splat2(bq.z), splat2(bq.w)};
#pragma unroll
            for (int p = 0; p < 4; p++)
#pragma unroll
                for (int j = 0; j < 4; j++) fma2(acc[p][j], ar[p], bs[j]);
        }
        __syncthreads();
    }

    // epilogue: bias + sigmoid + L2-normalize (row = warp)
    float4 bb = *(const float4*)(bias + tc * 4);
    float bv4[4] = {bb.x, bb.y, bb.z, bb.w};
#pragma unroll
    for (int p = 0; p < 4; p++) {
        float2 u[4];
#pragma unroll
        for (int j = 0; j < 4; j++) u[j] = unpack2(acc[p][j]);
#pragma unroll
        for (int h = 0; h < 2; h++) {
            int row = m0 + tr * 8 + p * 2 + h;
            float s[4];
            float sq = 0.f;
#pragma unroll
            for (int j = 0; j < 4; j++) {
                float v = (h ? u[j].y : u[j].x) + bv4[j];
                float sg = 1.f / (1.f + __expf(-v));
                s[j] = sg;
                sq += sg * sg;
            }
#pragma unroll
            for (int off = 16; off; off >>= 1)
                sq += __shfl_xor_sync(0xffffffffu, sq, off);
            float inv = 1.f / fmaxf(sqrtf(sq), 1e-12f);
            if (row < N_NODES) {
                float4 o;
                o.x = s[0] * inv; o.y = s[1] * inv;
                o.z = s[2] * inv; o.w = s[3] * inv;
                *(float4*)(g_h + (size_t)row * 128 + tc * 4) = o;
            }
        }
    }
}

// ---------------- layer 2 GEMM (FFMA2) + log_softmax epilogue ---------------
// Tile 64 x 256. Lane tc owns cols tc*8..tc*8+7; rows packed as 4 pairs.
__global__ void __launch_bounds__(256) k_gemm2(const float* __restrict__ Wl,
                                               const float* __restrict__ Wr,
                                               const float* __restrict__ bias,
                                               float* __restrict__ out) {
    __shared__ float As[BK * ASTRIDE];
    __shared__ float Bs[BK * 256];
    const int tid = threadIdx.x;
    const int tr = tid >> 5;
    const int tc = tid & 31;
    const int m0 = blockIdx.x * BM;

    u64 acc[4][8];   // [row-pair][col]
#pragma unroll
    for (int p = 0; p < 4; p++)
#pragma unroll
        for (int j = 0; j < 8; j++) acc[p][j] = 0ULL;

#pragma unroll 1
    for (int kc = 0; kc < 8; kc++) {
        const float* A = (kc < 4) ? (const float*)g_agg : (const float*)g_h;
        const float* W = (kc < 4) ? Wl : Wr;
        const int k0 = (kc & 3) * BK;

#pragma unroll
        for (int t = 0; t < 2; t++) {
            int idx = tid * 2 + t;
            int row = idx >> 3;
            int c4  = idx & 7;
            int gm  = m0 + row;
            float4 v = make_float4(0.f, 0.f, 0.f, 0.f);
            if (gm < N_NODES)
                v = *(const float4*)(A + (size_t)gm * 128 + k0 + c4 * 4);
            As[(c4 * 4 + 0) * ASTRIDE + row] = v.x;
            As[(c4 * 4 + 1) * ASTRIDE + row] = v.y;
            As[(c4 * 4 + 2) * ASTRIDE + row] = v.z;
            As[(c4 * 4 + 3) * ASTRIDE + row] = v.w;
        }
        // B tile: rows k0..k0+31 of W[128][256]  (2048 float4s, 8/thread)
#pragma unroll
        for (int t = 0; t < 8; t++) {
            int idx = tid + t * 256;        // 0..2047
            int row = idx >> 6;             // 0..31 (64 f4 per row)
            int c4  = idx & 63;
            *(float4*)&Bs[row * 256 + c4 * 4] =
                *(const float4*)(W + (size_t)(k0 + row) * 256 + c4 * 4);
        }
        __syncthreads();

#pragma unroll
        for (int k = 0; k < BK; k++) {
            ulonglong2 a01 = *(const ulonglong2*)&As[k * ASTRIDE + tr * 8];
            ulonglong2 a23 = *(const ulonglong2*)&As[k * ASTRIDE + tr * 8 + 4];
            float4 b0 = *(const float4*)&Bs[k * 256 + tc * 8];
            float4 b1 = *(const float4*)&Bs[k * 256 + tc * 8 + 4];
            u64 ar[4] = {a01.x, a01.y, a23.x, a23.y};
            u64 bs[8] = {splat2(b0.x), splat2(b0.y), splat2(b0.z), splat2(b0.w),
                         splat2(b1.x), splat2(b1.y), splat2(b1.z), splat2(b1.w)};
#pragma unroll
            for (int p = 0; p < 4; p++)
#pragma unroll
                for (int j = 0; j < 8; j++) fma2(acc[p][j], ar[p], bs[j]);
        }
        __syncthreads();
    }

    // epilogue: bias + sigmoid + L2-normalize + log_softmax (row = warp)
    float4 bq0 = *(const float4*)(bias + tc * 8);
    float4 bq1 = *(const float4*)(bias + tc * 8 + 4);
    float bv8[8] = {bq0.x, bq0.y, bq0.z, bq0.w, bq1.x, bq1.y, bq1.z, bq1.w};
#pragma unroll
    for (int p = 0; p < 4; p++) {
        float2 u[8];
#pragma unroll
        for (int j = 0; j < 8; j++) u[j] = unpack2(acc[p][j]);
#pragma unroll
        for (int h = 0; h < 2; h++) {
            int row = m0 + tr * 8 + p * 2 + h;
            float s[8];
            float sq = 0.f;
#pragma unroll
            for (int j = 0; j < 8; j++) {
                float v = (h ? u[j].y : u[j].x) + bv8[j];
                float sg = 1.f / (1.f + __expf(-v));
                s[j] = sg;
                sq += sg * sg;
            }
#pragma unroll
            for (int off = 16; off; off >>= 1)
                sq += __shfl_xor_sync(0xffffffffu, sq, off);
            float inv = 1.f / fmaxf(sqrtf(sq), 1e-12f);

            float mx = -1e30f;
#pragma unroll
            for (int j = 0; j < 8; j++) {
                float z = s[j] * inv;
                s[j] = z;
                mx = fmaxf(mx, z);
            }
#pragma unroll
            for (int off = 16; off; off >>= 1)
                mx = fmaxf(mx, __shfl_xor_sync(0xffffffffu, mx, off));

            float se = 0.f;
#pragma unroll
            for (int j = 0; j < 8; j++) se += __expf(s[j] - mx);
#pragma unroll
            for (int off = 16; off; off >>= 1)
                se += __shfl_xor_sync(0xffffffffu, se, off);
            float lse = mx + __logf(se);

            if (row < N_NODES) {
                float4 o0, o1;
                o0.x = s[0] - lse; o0.y = s[1] - lse;
                o0.z = s[2] - lse; o0.w = s[3] - lse;
                o1.x = s[4] - lse; o1.y = s[5] - lse;
                o1.z = s[6] - lse; o1.w = s[7] - lse;
                *(float4*)(out + (size_t)row * 256 + tc * 8)     = o0;
                *(float4*)(out + (size_t)row * 256 + tc * 8 + 4) = o1;
            }
        }
    }
}

// ---------------- launch -----------------
extern "C" void kernel_launch(void* const* d_in, const int* in_sizes, int n_in,
                              void* d_out, int out_size) {
    const float* x   = (const float*)d_in[0];
    const int*   ei  = (const int*)d_in[1];
    const float* W1l = (const float*)d_in[2];
    const float* W1r = (const float*)d_in[3];
    const float* b1  = (const float*)d_in[4];
    const float* W2l = (const float*)d_in[5];
    const float* W2r = (const float*)d_in[6];
    const float* b2  = (const float*)d_in[7];
    float* out = (float*)d_out;

    const int* src = ei;            // edge_index[0]
    const int* dst = ei + N_EDGES;  // edge_index[1]

    // CSR by destination
    k_zero_deg<<<(N_NODES + 255) / 256, 256>>>();
    k_count<<<592, 256>>>(dst);
    k_scan<<<1, 1024>>>();
    k_fill<<<592, 256>>>(src, dst);

    // layer 1
    k_agg<false><<<(N_NODES + 7) / 8, 256>>>(x);
    k_gemm1<<<(N_NODES + BM - 1) / BM, 256>>>(x, W1l, W1r, b1);

    // layer 2
    k_agg<true><<<(N_NODES + 7) / 8, 256>>>(x);
    k_gemm2<<<(N_NODES + BM - 1) / BM, 256>>>(W2l, W2r, b2, out);
}

// round 11
// speedup vs baseline: 1.4549x; 1.3835x over previous
#include <cuda_runtime.h>
#include <cuda_bf16.h>
#include <math.h>
#include <stdint.h>

#define N_NODES 50000
#define N_EDGES 800000
#define D_IN    128
#define D_HID   128
#define D_OUT   256

// ---------------- scratch (static device globals — no allocations) ----------
__device__ __align__(16) float g_h[(size_t)N_NODES * D_HID];
__device__ __align__(16) float g_agg[(size_t)N_NODES * D_IN];
__device__ int   g_deg[N_NODES];
__device__ int   g_row[N_NODES + 1];
__device__ int   g_cursor[N_NODES];
__device__ int   g_csr[N_EDGES];

// weights pre-transposed to [N][K=128], bf16 split hi/lo
__device__ __align__(16) __nv_bfloat16 g_w1lh[128 * 128], g_w1ll[128 * 128];
__device__ __align__(16) __nv_bfloat16 g_w1rh[128 * 128], g_w1rl[128 * 128];
__device__ __align__(16) __nv_bfloat16 g_w2lh[256 * 128], g_w2ll[256 * 128];
__device__ __align__(16) __nv_bfloat16 g_w2rh[256 * 128], g_w2rl[256 * 128];

// ---------------- helpers ----------------
__device__ __forceinline__ uint32_t smem_u32(const void* p) {
    uint32_t a;
    asm("{ .reg .u64 t; cvta.to.shared.u64 t, %1; cvt.u32.u64 %0, t; }"
        : "=r"(a) : "l"(p));
    return a;
}
__device__ __forceinline__ void ldsm4(uint32_t* r, uint32_t addr) {
    asm volatile("ldmatrix.sync.aligned.m8n8.x4.shared.b16 {%0,%1,%2,%3}, [%4];"
                 : "=r"(r[0]), "=r"(r[1]), "=r"(r[2]), "=r"(r[3]) : "r"(addr));
}
__device__ __forceinline__ void mma16816(float* c, const uint32_t* a,
                                         uint32_t b0, uint32_t b1) {
    asm volatile("mma.sync.aligned.m16n8k16.row.col.f32.bf16.bf16.f32 "
                 "{%0,%1,%2,%3}, {%4,%5,%6,%7}, {%8,%9}, {%0,%1,%2,%3};"
                 : "+f"(c[0]), "+f"(c[1]), "+f"(c[2]), "+f"(c[3])
                 : "r"(a[0]), "r"(a[1]), "r"(a[2]), "r"(a[3]), "r"(b0), "r"(b1));
}
#define STS128(addr, a, b, c, d)                                                \
    asm volatile("st.shared.v4.b32 [%0], {%1, %2, %3, %4};"                     \
                 :: "r"(addr), "r"(a), "r"(b), "r"(c), "r"(d) : "memory")

__device__ __forceinline__ float sigf(float v) { return 1.f / (1.f + __expf(-v)); }

// ---------------- weight prep: fp32 [K,N] -> bf16 hi/lo [N,K] ---------------
__global__ void k_prep_w(const float* __restrict__ W1l, const float* __restrict__ W1r,
                         const float* __restrict__ W2l, const float* __restrict__ W2r) {
    int i = blockIdx.x * blockDim.x + threadIdx.x;
    const float* W; __nv_bfloat16* H; __nv_bfloat16* L; int N; int t;
    if (i < 16384)      { W = W1l; H = g_w1lh; L = g_w1ll; N = 128; t = i; }
    else if (i < 32768) { W = W1r; H = g_w1rh; L = g_w1rl; N = 128; t = i - 16384; }
    else if (i < 65536) { W = W2l; H = g_w2lh; L = g_w2ll; N = 256; t = i - 32768; }
    else if (i < 98304) { W = W2r; H = g_w2rh; L = g_w2rl; N = 256; t = i - 65536; }
    else return;
    int n = t >> 7, k = t & 127;
    float v = W[k * N + n];
    __nv_bfloat16 h = __float2bfloat16(v);
    H[t] = h;
    L[t] = __float2bfloat16(v - __bfloat162float(h));
}

// ---------------- CSR build ----------------
__global__ void k_zero_deg() {
    int i = blockIdx.x * blockDim.x + threadIdx.x;
    if (i < N_NODES) g_deg[i] = 0;
}
__global__ void k_count(const int* __restrict__ dst) {
    for (int e = blockIdx.x * blockDim.x + threadIdx.x; e < N_EDGES;
         e += gridDim.x * blockDim.x)
        atomicAdd(&g_deg[dst[e]], 1);
}
__global__ void k_scan() {
    __shared__ int part[1024];
    const int tid = threadIdx.x;
    const int chunk = (N_NODES + 1023) / 1024;
    int base = tid * chunk;
    int s = 0;
    for (int j = 0; j < chunk; j++) {
        int idx = base + j;
        if (idx < N_NODES) s += g_deg[idx];
    }
    part[tid] = s;
    __syncthreads();
    for (int off = 1; off < 1024; off <<= 1) {
        int v = (tid >= off) ? part[tid - off] : 0;
        __syncthreads();
        part[tid] += v;
        __syncthreads();
    }
    int run = (tid > 0) ? part[tid - 1] : 0;
    for (int j = 0; j < chunk; j++) {
        int idx = base + j;
        if (idx < N_NODES) {
            g_row[idx] = run;
            g_cursor[idx] = run;
            run += g_deg[idx];
        }
    }
    if (tid == 1023) g_row[N_NODES] = part[1023];
}
__global__ void k_fill(const int* __restrict__ src, const int* __restrict__ dst) {
    for (int e = blockIdx.x * blockDim.x + threadIdx.x; e < N_EDGES;
         e += gridDim.x * blockDim.x) {
        int d = dst[e];
        int p = atomicAdd(&g_cursor[d], 1);
        g_csr[p] = src[e];
    }
}

// ---------------- mean aggregation: one warp per destination node -----------
template <bool USE_H>
__global__ void __launch_bounds__(256) k_agg(const float* __restrict__ xin) {
    const float* __restrict__ feat = USE_H ? (const float*)g_h : xin;
    int warp = threadIdx.x >> 5;
    int lane = threadIdx.x & 31;
    int node = blockIdx.x * 8 + warp;
    if (node >= N_NODES) return;
    int s = g_row[node];
    int e = g_row[node + 1];

    float4 a0 = make_float4(0.f, 0.f, 0.f, 0.f);
    float4 a1 = make_float4(0.f, 0.f, 0.f, 0.f);
    float4 a2 = make_float4(0.f, 0.f, 0.f, 0.f);
    float4 a3 = make_float4(0.f, 0.f, 0.f, 0.f);
    int i = s;
    for (; i + 3 < e; i += 4) {
        int u0 = g_csr[i];
        int u1 = g_csr[i + 1];
        int u2 = g_csr[i + 2];
        int u3 = g_csr[i + 3];
        float4 v0 = *(const float4*)(feat + (size_t)u0 * 128 + lane * 4);
        float4 v1 = *(const float4*)(feat + (size_t)u1 * 128 + lane * 4);
        float4 v2 = *(const float4*)(feat + (size_t)u2 * 128 + lane * 4);
        float4 v3 = *(const float4*)(feat + (size_t)u3 * 128 + lane * 4);
        a0.x += v0.x; a0.y += v0.y; a0.z += v0.z; a0.w += v0.w;
        a1.x += v1.x; a1.y += v1.y; a1.z += v1.z; a1.w += v1.w;
        a2.x += v2.x; a2.y += v2.y; a2.z += v2.z; a2.w += v2.w;
        a3.x += v3.x; a3.y += v3.y; a3.z += v3.z; a3.w += v3.w;
    }
    for (; i < e; i++) {
        int u0 = g_csr[i];
        float4 v0 = *(const float4*)(feat + (size_t)u0 * 128 + lane * 4);
        a0.x += v0.x; a0.y += v0.y; a0.z += v0.z; a0.w += v0.w;
    }
    float invd = (e > s) ? 1.f / (float)(e - s) : 0.f;
    float4 r;
    r.x = (a0.x + a1.x + a2.x + a3.x) * invd;
    r.y = (a0.y + a1.y + a2.y + a3.y) * invd;
    r.z = (a0.z + a1.z + a2.z + a3.z) * invd;
    r.w = (a0.w + a1.w + a2.w + a3.w) * invd;
    *(float4*)(g_agg + (size_t)node * 128 + lane * 4) = r;
}

// ---------------- tensor-core GEMM (mma.sync bf16, 3-term split) ------------
// Block: 64 rows x N_OUT cols, 256 threads = 8 warps (2M x 4N).
// Warp tile: 32 x (N_OUT/4).  K chunked by 32 over (agg|self) x 4.
// smem: Ah/Al [64x32 bf16], Bh/Bl [N_OUT x 32 bf16], 16B-group XOR swizzle
//   group' = g ^ ((row>>1)&3)  -> conflict-free STS128 and ldmatrix.
template <int LAYER>
__global__ void __launch_bounds__(256) k_mma(const float* __restrict__ xin,
                                             const float* __restrict__ bias,
                                             float* __restrict__ outp) {
    constexpr int N_OUT = (LAYER == 1) ? 128 : 256;
    constexpr int NFRAG = N_OUT / 32;           // n8 frags per warp (4 or 8)
    constexpr int NX4   = NFRAG / 2;            // ldmatrix.x4 per B operand per k16
    constexpr int WN    = N_OUT / 4;            // warp tile width
    constexpr int OFF_AL = 4096;
    constexpr int OFF_BH = 8192;
    constexpr int BOFF   = N_OUT * 64;          // Bh->Bl byte offset
    constexpr int OFF_RED = 8192 + 2 * BOFF;
    constexpr int SM_BYTES = OFF_RED + 1024 * ((LAYER == 1) ? 1 : 3);

    __shared__ __align__(16) char sm[SM_BYTES];
    const uint32_t sb = smem_u32(sm);

    const int tid = threadIdx.x;
    const int wid = tid >> 5;
    const int lane = tid & 31;
    const int warpM = wid >> 2;                 // 0..1
    const int warpN = wid & 3;                  // 0..3
    const int m0 = blockIdx.x * 64;

    const float* A0 = g_agg;
    const float* A1 = (LAYER == 1) ? xin : (const float*)g_h;
    const __nv_bfloat16* B0h = (LAYER == 1) ? g_w1lh : g_w2lh;
    const __nv_bfloat16* B0l = (LAYER == 1) ? g_w1ll : g_w2ll;
    const __nv_bfloat16* B1h = (LAYER == 1) ? g_w1rh : g_w2rh;
    const __nv_bfloat16* B1l = (LAYER == 1) ? g_w1rl : g_w2rl;
    float* dst = (LAYER == 1) ? (float*)g_h : outp;

    float acc[2][NFRAG][4];
#pragma unroll
    for (int mi = 0; mi < 2; mi++)
#pragma unroll
        for (int nj = 0; nj < NFRAG; nj++)
#pragma unroll
            for (int c = 0; c < 4; c++) acc[mi][nj][c] = 0.f;

    // precomputed ldmatrix addresses (smem layout identical every chunk)
    uint32_t a_addr[2][2];
#pragma unroll
    for (int mi = 0; mi < 2; mi++) {
        int row = warpM * 32 + mi * 16 + (lane & 7) + ((lane >> 3) & 1) * 8;
#pragma unroll
        for (int k2 = 0; k2 < 2; k2++) {
            int kg = k2 * 2 + (lane >> 4);
            int gs = kg ^ ((row >> 1) & 3);
            a_addr[mi][k2] = sb + row * 64 + gs * 16;
        }
    }
    uint32_t b_addr[NX4][2];
#pragma unroll
    for (int q = 0; q < NX4; q++) {
        int n = warpN * WN + q * 16 + (lane & 7) + ((lane >> 4) & 1) * 8;
#pragma unroll
        for (int k2 = 0; k2 < 2; k2++) {
            int kg = k2 * 2 + ((lane >> 3) & 1);
            int gs = kg ^ ((n >> 1) & 3);
            b_addr[q][k2] = sb + OFF_BH + n * 64 + gs * 16;
        }
    }

#pragma unroll 1
    for (int chunk = 0; chunk < 8; chunk++) {
        const int srci = chunk >> 2;
        const int k0 = (chunk & 3) * 32;
        const float* Aptr = srci ? A1 : A0;
        const __nv_bfloat16* Bh = srci ? B1h : B0h;
        const __nv_bfloat16* Bl = srci ? B1l : B0l;

        // ---- A tile: fp32 -> bf16 hi/lo, swizzled ----
        {
            int r = tid >> 2, g = tid & 3;
            int gm = m0 + r;
            float v[8];
            if (gm < N_NODES) {
                const float* p = Aptr + (size_t)gm * 128 + k0 + g * 8;
                float4 p0 = *(const float4*)p;
                float4 p1 = *(const float4*)(p + 4);
                v[0] = p0.x; v[1] = p0.y; v[2] = p0.z; v[3] = p0.w;
                v[4] = p1.x; v[5] = p1.y; v[6] = p1.z; v[7] = p1.w;
            } else {
#pragma unroll
                for (int j = 0; j < 8; j++) v[j] = 0.f;
            }
            uint32_t hw[4], lw[4];
#pragma unroll
            for (int j = 0; j < 4; j++) {
                float a = v[2 * j], b = v[2 * j + 1];
                __nv_bfloat16 ah = __float2bfloat16(a);
                __nv_bfloat16 bh2 = __float2bfloat16(b);
                __nv_bfloat162 hp; hp.x = ah; hp.y = bh2;
                __nv_bfloat162 lp = __floats2bfloat162_rn(a - __bfloat162float(ah),
                                                          b - __bfloat162float(bh2));
                hw[j] = *(uint32_t*)&hp;
                lw[j] = *(uint32_t*)&lp;
            }
            int gs = g ^ ((r >> 1) & 3);
            uint32_t off = sb + r * 64 + gs * 16;
            STS128(off, hw[0], hw[1], hw[2], hw[3]);
            STS128(off + OFF_AL, lw[0], lw[1], lw[2], lw[3]);
        }
        // ---- B tile: prepped bf16 [N,128] -> swizzled smem ----
#pragma unroll
        for (int t = 0; t < N_OUT / 64; t++) {
            int idx = tid + t * 256;
            int r = idx >> 2, g = idx & 3;
            const char* ph = (const char*)Bh + r * 256 + k0 * 2 + g * 16;
            const char* pl = (const char*)Bl + r * 256 + k0 * 2 + g * 16;
            uint4 vh = *(const uint4*)ph;
            uint4 vl = *(const uint4*)pl;
            int gs = g ^ ((r >> 1) & 3);
            uint32_t off = sb + OFF_BH + r * 64 + gs * 16;
            STS128(off, vh.x, vh.y, vh.z, vh.w);
            STS128(off + BOFF, vl.x, vl.y, vl.z, vl.w);
        }
        __syncthreads();

#pragma unroll
        for (int k2 = 0; k2 < 2; k2++) {
            uint32_t ah[2][4], al[2][4];
            ldsm4(ah[0], a_addr[0][k2]);
            ldsm4(ah[1], a_addr[1][k2]);
            ldsm4(al[0], a_addr[0][k2] + OFF_AL);
            ldsm4(al[1], a_addr[1][k2] + OFF_AL);
#pragma unroll
            for (int q = 0; q < NX4; q++) {
                uint32_t bh[4], bl[4];
                ldsm4(bh, b_addr[q][k2]);
                ldsm4(bl, b_addr[q][k2] + BOFF);
#pragma unroll
                for (int s = 0; s < 2; s++) {
#pragma unroll
                    for (int mi = 0; mi < 2; mi++) {
                        float* c = acc[mi][2 * q + s];
                        mma16816(c, ah[mi], bh[2 * s], bh[2 * s + 1]);
                        mma16816(c, ah[mi], bl[2 * s], bl[2 * s + 1]);
                        mma16816(c, al[mi], bh[2 * s], bh[2 * s + 1]);
                    }
                }
            }
        }
        __syncthreads();
    }

    // ---- epilogue ----------------------------------------------------------
    const int quad = lane >> 2;
    const int qt = lane & 3;
    float* redq = (float*)(sm + OFF_RED);

    // bias + sigmoid in place
#pragma unroll
    for (int mi = 0; mi < 2; mi++)
#pragma unroll
        for (int nj = 0; nj < NFRAG; nj++)
#pragma unroll
            for (int c = 0; c < 4; c++) {
                int col = warpN * WN + nj * 8 + qt * 2 + (c & 1);
                acc[mi][nj][c] = sigf(acc[mi][nj][c] + __ldg(bias + col));
            }

    // L2-norm partial (quad butterfly + cross-warpN smem reduce)
#pragma unroll
    for (int mi = 0; mi < 2; mi++)
#pragma unroll
        for (int half = 0; half < 2; half++) {
            float sq = 0.f;
#pragma unroll
            for (int nj = 0; nj < NFRAG; nj++) {
                float u0 = acc[mi][nj][half * 2], u1 = acc[mi][nj][half * 2 + 1];
                sq += u0 * u0 + u1 * u1;
            }
            sq += __shfl_xor_sync(0xffffffffu, sq, 1);
            sq += __shfl_xor_sync(0xffffffffu, sq, 2);
            int row = warpM * 32 + mi * 16 + quad + half * 8;
            if (qt == 0) redq[row * 4 + warpN] = sq;
        }
    __syncthreads();

    float inv[2][2];
#pragma unroll
    for (int mi = 0; mi < 2; mi++)
#pragma unroll
        for (int half = 0; half < 2; half++) {
            int row = warpM * 32 + mi * 16 + quad + half * 8;
            float t = redq[row * 4] + redq[row * 4 + 1] + redq[row * 4 + 2] +
                      redq[row * 4 + 3];
            inv[mi][half] = 1.f / fmaxf(sqrtf(t), 1e-12f);
        }

    if (LAYER == 1) {
#pragma unroll
        for (int mi = 0; mi < 2; mi++)
#pragma unroll
            for (int half = 0; half < 2; half++) {
                int row = warpM * 32 + mi * 16 + quad + half * 8;
                int gm = m0 + row;
                if (gm < N_NODES) {
#pragma unroll
                    for (int nj = 0; nj < NFRAG; nj++) {
                        float2 o;
                        o.x = acc[mi][nj][half * 2] * inv[mi][half];
                        o.y = acc[mi][nj][half * 2 + 1] * inv[mi][half];
                        *(float2*)(dst + (size_t)gm * N_OUT + warpN * WN + nj * 8 +
                                   qt * 2) = o;
                    }
                }
            }
    } else {
        float* redm = (float*)(sm + OFF_RED + 1024);
        float* reds = (float*)(sm + OFF_RED + 2048);
        // z = sig * inv (overwrite), local max
#pragma unroll
        for (int mi = 0; mi < 2; mi++)
#pragma unroll
            for (int half = 0; half < 2; half++) {
                float mx = -1e30f;
#pragma unroll
                for (int nj = 0; nj < NFRAG; nj++) {
                    float z0 = acc[mi][nj][half * 2] * inv[mi][half];
                    float z1 = acc[mi][nj][half * 2 + 1] * inv[mi][half];
                    acc[mi][nj][half * 2] = z0;
                    acc[mi][nj][half * 2 + 1] = z1;
                    mx = fmaxf(mx, fmaxf(z0, z1));
                }
                mx = fmaxf(mx, __shfl_xor_sync(0xffffffffu, mx, 1));
                mx = fmaxf(mx, __shfl_xor_sync(0xffffffffu, mx, 2));
                int row = warpM * 32 + mi * 16 + quad + half * 8;
                if (qt == 0) redm[row * 4 + warpN] = mx;
            }
        __syncthreads();
        float mxr[2][2];
#pragma unroll
        for (int mi = 0; mi < 2; mi++)
#pragma unroll
            for (int half = 0; half < 2; half++) {
                int row = warpM * 32 + mi * 16 + quad + half * 8;
                mxr[mi][half] = fmaxf(fmaxf(redm[row * 4], redm[row * 4 + 1]),
                                      fmaxf(redm[row * 4 + 2], redm[row * 4 + 3]));
            }
        // sum exp
#pragma unroll
        for (int mi = 0; mi < 2; mi++)
#pragma unroll
            for (int half = 0; half < 2; half++) {
                float se = 0.f;
#pragma unroll
                for (int nj = 0; nj < NFRAG; nj++) {
                    se += __expf(acc[mi][nj][half * 2] - mxr[mi][half]);
                    se += __expf(acc[mi][nj][half * 2 + 1] - mxr[mi][half]);
                }
                se += __shfl_xor_sync(0xffffffffu, se, 1);
                se += __shfl_xor_sync(0xffffffffu, se, 2);
                int row = warpM * 32 + mi * 16 + quad + half * 8;
                if (qt == 0) reds[row * 4 + warpN] = se;
            }
        __syncthreads();
#pragma unroll
        for (int mi = 0; mi < 2; mi++)
#pragma unroll
            for (int half = 0; half < 2; half++) {
                int row = warpM * 32 + mi * 16 + quad + half * 8;
                float se = reds[row * 4] + reds[row * 4 + 1] + reds[row * 4 + 2] +
                           reds[row * 4 + 3];
                float lse = mxr[mi][half] + __logf(se);
                int gm = m0 + row;
                if (gm < N_NODES) {
#pragma unroll
                    for (int nj = 0; nj < NFRAG; nj++) {
                        float2 o;
                        o.x = acc[mi][nj][half * 2] - lse;
                        o.y = acc[mi][nj][half * 2 + 1] - lse;
                        *(float2*)(dst + (size_t)gm * N_OUT + warpN * WN + nj * 8 +
                                   qt * 2) = o;
                    }
                }
            }
    }
}

// ---------------- launch -----------------
extern "C" void kernel_launch(void* const* d_in, const int* in_sizes, int n_in,
                              void* d_out, int out_size) {
    const float* x   = (const float*)d_in[0];
    const int*   ei  = (const int*)d_in[1];
    const float* W1l = (const float*)d_in[2];
    const float* W1r = (const float*)d_in[3];
    const float* b1  = (const float*)d_in[4];
    const float* W2l = (const float*)d_in[5];
    const float* W2r = (const float*)d_in[6];
    const float* b2  = (const float*)d_in[7];
    float* out = (float*)d_out;

    const int* src = ei;            // edge_index[0]
    const int* dst = ei + N_EDGES;  // edge_index[1]

    // weight prep (bf16 split + transpose)
    k_prep_w<<<384, 256>>>(W1l, W1r, W2l, W2r);

    // CSR by destination
    k_zero_deg<<<(N_NODES + 255) / 256, 256>>>();
    k_count<<<592, 256>>>(dst);
    k_scan<<<1, 1024>>>();
    k_fill<<<592, 256>>>(src, dst);

    const int gblocks = (N_NODES + 63) / 64;   // 782

    // layer 1
    k_agg<false><<<(N_NODES + 7) / 8, 256>>>(x);
    k_mma<1><<<gblocks, 256>>>(x, b1, out);

    // layer 2
    k_agg<true><<<(N_NODES + 7) / 8, 256>>>(x);
    k_mma<2><<<gblocks, 256>>>(x, b2, out);
}

// round 12
// speedup vs baseline: 1.9282x; 1.3253x over previous
#include <cuda_runtime.h>
#include <cuda_bf16.h>
#include <math.h>
#include <stdint.h>

#define N_NODES 50000
#define N_EDGES 800000
#define D_IN    128
#define D_HID   128
#define D_OUT   256
#define SCAN_BLOCKS 196   // ceil(N_NODES/256)

// ---------------- scratch (static device globals — no allocations) ----------
__device__ __align__(16) float g_h[(size_t)N_NODES * D_HID];
__device__ __align__(16) float g_agg[(size_t)N_NODES * D_IN];
__device__ int   g_deg[N_NODES];
__device__ int   g_row[N_NODES + 1];
__device__ int   g_cursor[N_NODES];
__device__ int   g_csr[N_EDGES];
__device__ int   g_stmp[N_NODES];
__device__ int   g_bsum[SCAN_BLOCKS];
__device__ int   g_boff[SCAN_BLOCKS];

// weights pre-transposed to [N][K=128], bf16 split hi/lo
__device__ __align__(16) __nv_bfloat16 g_w1lh[128 * 128], g_w1ll[128 * 128];
__device__ __align__(16) __nv_bfloat16 g_w1rh[128 * 128], g_w1rl[128 * 128];
__device__ __align__(16) __nv_bfloat16 g_w2lh[256 * 128], g_w2ll[256 * 128];
__device__ __align__(16) __nv_bfloat16 g_w2rh[256 * 128], g_w2rl[256 * 128];

// ---------------- helpers ----------------
__device__ __forceinline__ uint32_t smem_u32(const void* p) {
    uint32_t a;
    asm("{ .reg .u64 t; cvta.to.shared.u64 t, %1; cvt.u32.u64 %0, t; }"
        : "=r"(a) : "l"(p));
    return a;
}
__device__ __forceinline__ void ldsm4(uint32_t* r, uint32_t addr) {
    asm volatile("ldmatrix.sync.aligned.m8n8.x4.shared.b16 {%0,%1,%2,%3}, [%4];"
                 : "=r"(r[0]), "=r"(r[1]), "=r"(r[2]), "=r"(r[3]) : "r"(addr));
}
__device__ __forceinline__ void mma16816(float* c, const uint32_t* a,
                                         uint32_t b0, uint32_t b1) {
    asm volatile("mma.sync.aligned.m16n8k16.row.col.f32.bf16.bf16.f32 "
                 "{%0,%1,%2,%3}, {%4,%5,%6,%7}, {%8,%9}, {%0,%1,%2,%3};"
                 : "+f"(c[0]), "+f"(c[1]), "+f"(c[2]), "+f"(c[3])
                 : "r"(a[0]), "r"(a[1]), "r"(a[2]), "r"(a[3]), "r"(b0), "r"(b1));
}
#define STS128(addr, a, b, c, d)                                                \
    asm volatile("st.shared.v4.b32 [%0], {%1, %2, %3, %4};"                     \
                 :: "r"(addr), "r"(a), "r"(b), "r"(c), "r"(d) : "memory")

__device__ __forceinline__ float sigf(float v) { return 1.f / (1.f + __expf(-v)); }

__device__ __forceinline__ int warp_incl_scan(int v, int lane) {
#pragma unroll
    for (int off = 1; off < 32; off <<= 1) {
        int n = __shfl_up_sync(0xffffffffu, v, off);
        if (lane >= off) v += n;
    }
    return v;
}

// ---------------- weight prep: fp32 [K,N] -> bf16 hi/lo [N,K] ---------------
__global__ void k_prep_w(const float* __restrict__ W1l, const float* __restrict__ W1r,
                         const float* __restrict__ W2l, const float* __restrict__ W2r) {
    int i = blockIdx.x * blockDim.x + threadIdx.x;
    const float* W; __nv_bfloat16* H; __nv_bfloat16* L; int N; int t;
    if (i < 16384)      { W = W1l; H = g_w1lh; L = g_w1ll; N = 128; t = i; }
    else if (i < 32768) { W = W1r; H = g_w1rh; L = g_w1rl; N = 128; t = i - 16384; }
    else if (i < 65536) { W = W2l; H = g_w2lh; L = g_w2ll; N = 256; t = i - 32768; }
    else if (i < 98304) { W = W2r; H = g_w2rh; L = g_w2rl; N = 256; t = i - 65536; }
    else return;
    int n = t >> 7, k = t & 127;
    float v = W[k * N + n];
    __nv_bfloat16 h = __float2bfloat16(v);
    H[t] = h;
    L[t] = __float2bfloat16(v - __bfloat162float(h));
}

// ---------------- CSR build ----------------
__global__ void k_zero_deg() {
    int i = blockIdx.x * blockDim.x + threadIdx.x;
    if (i < N_NODES) g_deg[i] = 0;
}
__global__ void k_count(const int* __restrict__ dst) {
    for (int e = blockIdx.x * blockDim.x + threadIdx.x; e < N_EDGES;
         e += gridDim.x * blockDim.x)
        atomicAdd(&g_deg[dst[e]], 1);
}

// ---- 3-phase coalesced scan (replaces the 80us single-block scan) ----------
__global__ void k_scan1() {
    __shared__ int wsum[8];
    const int t = threadIdx.x;
    const int i = blockIdx.x * 256 + t;
    const int lane = t & 31, w = t >> 5;
    int d = (i < N_NODES) ? g_deg[i] : 0;
    int v = warp_incl_scan(d, lane);
    if (lane == 31) wsum[w] = v;
    __syncthreads();
    if (w == 0) {
        int s = (lane < 8) ? wsum[lane] : 0;
#pragma unroll
        for (int off = 1; off < 8; off <<= 1) {
            int n = __shfl_up_sync(0xffffffffu, s, off);
            if (lane >= off) s += n;
        }
        if (lane < 8) wsum[lane] = s;
    }
    __syncthreads();
    int incl = v + (w ? wsum[w - 1] : 0);
    if (i < N_NODES) g_stmp[i] = incl - d;            // exclusive within block
    if (t == 255) g_bsum[blockIdx.x] = incl;          // block total
}

__global__ void k_scan2() {
    __shared__ int wsum[8];
    const int t = threadIdx.x;
    const int lane = t & 31, w = t >> 5;
    int d = (t < SCAN_BLOCKS) ? g_bsum[t] : 0;
    int v = warp_incl_scan(d, lane);
    if (lane == 31) wsum[w] = v;
    __syncthreads();
    if (w == 0) {
        int s = (lane < 8) ? wsum[lane] : 0;
#pragma unroll
        for (int off = 1; off < 8; off <<= 1) {
            int n = __shfl_up_sync(0xffffffffu, s, off);
            if (lane >= off) s += n;
        }
        if (lane < 8) wsum[lane] = s;
    }
    __syncthreads();
    int incl = v + (w ? wsum[w - 1] : 0);
    if (t < SCAN_BLOCKS) g_boff[t] = incl - d;        // exclusive block offset
}

__global__ void k_scan3() {
    const int i = blockIdx.x * 256 + threadIdx.x;
    if (i < N_NODES) {
        int r = g_stmp[i] + g_boff[i >> 8];
        g_row[i] = r;
        g_cursor[i] = r;
    }
    if (i == 0) g_row[N_NODES] = N_EDGES;             // every dst is a node
}

__global__ void k_fill(const int* __restrict__ src, const int* __restrict__ dst) {
    for (int e = blockIdx.x * blockDim.x + threadIdx.x; e < N_EDGES;
         e += gridDim.x * blockDim.x) {
        int d = dst[e];
        int p = atomicAdd(&g_cursor[d], 1);
        g_csr[p] = src[e];
    }
}

// ---------------- mean aggregation: one warp per destination node -----------
template <bool USE_H>
__global__ void __launch_bounds__(256) k_agg(const float* __restrict__ xin) {
    const float* __restrict__ feat = USE_H ? (const float*)g_h : xin;
    int warp = threadIdx.x >> 5;
    int lane = threadIdx.x & 31;
    int node = blockIdx.x * 8 + warp;
    if (node >= N_NODES) return;
    int s = g_row[node];
    int e = g_row[node + 1];

    float4 a0 = make_float4(0.f, 0.f, 0.f, 0.f);
    float4 a1 = make_float4(0.f, 0.f, 0.f, 0.f);
    float4 a2 = make_float4(0.f, 0.f, 0.f, 0.f);
    float4 a3 = make_float4(0.f, 0.f, 0.f, 0.f);
    int i = s;
    for (; i + 3 < e; i += 4) {
        int u0 = g_csr[i];
        int u1 = g_csr[i + 1];
        int u2 = g_csr[i + 2];
        int u3 = g_csr[i + 3];
        float4 v0 = *(const float4*)(feat + (size_t)u0 * 128 + lane * 4);
        float4 v1 = *(const float4*)(feat + (size_t)u1 * 128 + lane * 4);
        float4 v2 = *(const float4*)(feat + (size_t)u2 * 128 + lane * 4);
        float4 v3 = *(const float4*)(feat + (size_t)u3 * 128 + lane * 4);
        a0.x += v0.x; a0.y += v0.y; a0.z += v0.z; a0.w += v0.w;
        a1.x += v1.x; a1.y += v1.y; a1.z += v1.z; a1.w += v1.w;
        a2.x += v2.x; a2.y += v2.y; a2.z += v2.z; a2.w += v2.w;
        a3.x += v3.x; a3.y += v3.y; a3.z += v3.z; a3.w += v3.w;
    }
    for (; i < e; i++) {
        int u0 = g_csr[i];
        float4 v0 = *(const float4*)(feat + (size_t)u0 * 128 + lane * 4);
        a0.x += v0.x; a0.y += v0.y; a0.z += v0.z; a0.w += v0.w;
    }
    float invd = (e > s) ? 1.f / (float)(e - s) : 0.f;
    float4 r;
    r.x = (a0.x + a1.x + a2.x + a3.x) * invd;
    r.y = (a0.y + a1.y + a2.y + a3.y) * invd;
    r.z = (a0.z + a1.z + a2.z + a3.z) * invd;
    r.w = (a0.w + a1.w + a2.w + a3.w) * invd;
    *(float4*)(g_agg + (size_t)node * 128 + lane * 4) = r;
}

// ---------------- tensor-core GEMM (mma.sync bf16, 3-term split) ------------
// Block: 64 rows x N_OUT cols, 256 threads = 8 warps (2M x 4N).
// Warp tile: 32 x (N_OUT/4).  K chunked by 32 over (agg|self) x 4.
// smem: Ah/Al [64x32 bf16], Bh/Bl [N_OUT x 32 bf16], 16B-group XOR swizzle.
template <int LAYER>
__global__ void __launch_bounds__(256) k_mma(const float* __restrict__ xin,
                                             const float* __restrict__ bias,
                                             float* __restrict__ outp) {
    constexpr int N_OUT = (LAYER == 1) ? 128 : 256;
    constexpr int NFRAG = N_OUT / 32;
    constexpr int NX4   = NFRAG / 2;
    constexpr int WN    = N_OUT / 4;
    constexpr int OFF_AL = 4096;
    constexpr int OFF_BH = 8192;
    constexpr int BOFF   = N_OUT * 64;
    constexpr int OFF_RED = 8192 + 2 * BOFF;
    constexpr int SM_BYTES = OFF_RED + 1024 * ((LAYER == 1) ? 1 : 3);

    __shared__ __align__(16) char sm[SM_BYTES];
    const uint32_t sb = smem_u32(sm);

    const int tid = threadIdx.x;
    const int wid = tid >> 5;
    const int lane = tid & 31;
    const int warpM = wid >> 2;
    const int warpN = wid & 3;
    const int m0 = blockIdx.x * 64;

    const float* A0 = g_agg;
    const float* A1 = (LAYER == 1) ? xin : (const float*)g_h;
    const __nv_bfloat16* B0h = (LAYER == 1) ? g_w1lh : g_w2lh;
    const __nv_bfloat16* B0l = (LAYER == 1) ? g_w1ll : g_w2ll;
    const __nv_bfloat16* B1h = (LAYER == 1) ? g_w1rh : g_w2rh;
    const __nv_bfloat16* B1l = (LAYER == 1) ? g_w1rl : g_w2rl;
    float* dst = (LAYER == 1) ? (float*)g_h : outp;

    float acc[2][NFRAG][4];
#pragma unroll
    for (int mi = 0; mi < 2; mi++)
#pragma unroll
        for (int nj = 0; nj < NFRAG; nj++)
#pragma unroll
            for (int c = 0; c < 4; c++) acc[mi][nj][c] = 0.f;

    uint32_t a_addr[2][2];
#pragma unroll
    for (int mi = 0; mi < 2; mi++) {
        int row = warpM * 32 + mi * 16 + (lane & 7) + ((lane >> 3) & 1) * 8;
#pragma unroll
        for (int k2 = 0; k2 < 2; k2++) {
            int kg = k2 * 2 + (lane >> 4);
            int gs = kg ^ ((row >> 1) & 3);
            a_addr[mi][k2] = sb + row * 64 + gs * 16;
        }
    }
    uint32_t b_addr[NX4][2];
#pragma unroll
    for (int q = 0; q < NX4; q++) {
        int n = warpN * WN + q * 16 + (lane & 7) + ((lane >> 4) & 1) * 8;
#pragma unroll
        for (int k2 = 0; k2 < 2; k2++) {
            int kg = k2 * 2 + ((lane >> 3) & 1);
            int gs = kg ^ ((n >> 1) & 3);
            b_addr[q][k2] = sb + OFF_BH + n * 64 + gs * 16;
        }
    }

#pragma unroll 1
    for (int chunk = 0; chunk < 8; chunk++) {
        const int srci = chunk >> 2;
        const int k0 = (chunk & 3) * 32;
        const float* Aptr = srci ? A1 : A0;
        const __nv_bfloat16* Bh = srci ? B1h : B0h;
        const __nv_bfloat16* Bl = srci ? B1l : B0l;

        // ---- A tile: fp32 -> bf16 hi/lo, swizzled ----
        {
            int r = tid >> 2, g = tid & 3;
            int gm = m0 + r;
            float v[8];
            if (gm < N_NODES) {
                const float* p = Aptr + (size_t)gm * 128 + k0 + g * 8;
                float4 p0 = *(const float4*)p;
                float4 p1 = *(const float4*)(p + 4);
                v[0] = p0.x; v[1] = p0.y; v[2] = p0.z; v[3] = p0.w;
                v[4] = p1.x; v[5] = p1.y; v[6] = p1.z; v[7] = p1.w;
            } else {
#pragma unroll
                for (int j = 0; j < 8; j++) v[j] = 0.f;
            }
            uint32_t hw[4], lw[4];
#pragma unroll
            for (int j = 0; j < 4; j++) {
                float a = v[2 * j], b = v[2 * j + 1];
                __nv_bfloat16 ah = __float2bfloat16(a);
                __nv_bfloat16 bh2 = __float2bfloat16(b);
                __nv_bfloat162 hp; hp.x = ah; hp.y = bh2;
                __nv_bfloat162 lp = __floats2bfloat162_rn(a - __bfloat162float(ah),
                                                          b - __bfloat162float(bh2));
                hw[j] = *(uint32_t*)&hp;
                lw[j] = *(uint32_t*)&lp;
            }
            int gs = g ^ ((r >> 1) & 3);
            uint32_t off = sb + r * 64 + gs * 16;
            STS128(off, hw[0], hw[1], hw[2], hw[3]);
            STS128(off + OFF_AL, lw[0], lw[1], lw[2], lw[3]);
        }
        // ---- B tile: prepped bf16 [N,128] -> swizzled smem ----
#pragma unroll
        for (int t = 0; t < N_OUT / 64; t++) {
            int idx = tid + t * 256;
            int r = idx >> 2, g = idx & 3;
            const char* ph = (const char*)Bh + r * 256 + k0 * 2 + g * 16;
            const char* pl = (const char*)Bl + r * 256 + k0 * 2 + g * 16;
            uint4 vh = *(const uint4*)ph;
            uint4 vl = *(const uint4*)pl;
            int gs = g ^ ((r >> 1) & 3);
            uint32_t off = sb + OFF_BH + r * 64 + gs * 16;
            STS128(off, vh.x, vh.y, vh.z, vh.w);
            STS128(off + BOFF, vl.x, vl.y, vl.z, vl.w);
        }
        __syncthreads();

#pragma unroll
        for (int k2 = 0; k2 < 2; k2++) {
            uint32_t ah[2][4], al[2][4];
            ldsm4(ah[0], a_addr[0][k2]);
            ldsm4(ah[1], a_addr[1][k2]);
            ldsm4(al[0], a_addr[0][k2] + OFF_AL);
            ldsm4(al[1], a_addr[1][k2] + OFF_AL);
#pragma unroll
            for (int q = 0; q < NX4; q++) {
                uint32_t bh[4], bl[4];
                ldsm4(bh, b_addr[q][k2]);
                ldsm4(bl, b_addr[q][k2] + BOFF);
#pragma unroll
                for (int s = 0; s < 2; s++) {
#pragma unroll
                    for (int mi = 0; mi < 2; mi++) {
                        float* c = acc[mi][2 * q + s];
                        mma16816(c, ah[mi], bh[2 * s], bh[2 * s + 1]);
                        mma16816(c, ah[mi], bl[2 * s], bl[2 * s + 1]);
                        mma16816(c, al[mi], bh[2 * s], bh[2 * s + 1]);
                    }
                }
            }
        }
        __syncthreads();
    }

    // ---- epilogue ----------------------------------------------------------
    const int quad = lane >> 2;
    const int qt = lane & 3;
    float* redq = (float*)(sm + OFF_RED);

#pragma unroll
    for (int mi = 0; mi < 2; mi++)
#pragma unroll
        for (int nj = 0; nj < NFRAG; nj++)
#pragma unroll
            for (int c = 0; c < 4; c++) {
                int col = warpN * WN + nj * 8 + qt * 2 + (c & 1);
                acc[mi][nj][c] = sigf(acc[mi][nj][c] + __ldg(bias + col));
            }

#pragma unroll
    for (int mi = 0; mi < 2; mi++)
#pragma unroll
        for (int half = 0; half < 2; half++) {
            float sq = 0.f;
#pragma unroll
            for (int nj = 0; nj < NFRAG; nj++) {
                float u0 = acc[mi][nj][half * 2], u1 = acc[mi][nj][half * 2 + 1];
                sq += u0 * u0 + u1 * u1;
            }
            sq += __shfl_xor_sync(0xffffffffu, sq, 1);
            sq += __shfl_xor_sync(0xffffffffu, sq, 2);
            int row = warpM * 32 + mi * 16 + quad + half * 8;
            if (qt == 0) redq[row * 4 + warpN] = sq;
        }
    __syncthreads();

    float inv[2][2];
#pragma unroll
    for (int mi = 0; mi < 2; mi++)
#pragma unroll
        for (int half = 0; half < 2; half++) {
            int row = warpM * 32 + mi * 16 + quad + half * 8;
            float t = redq[row * 4] + redq[row * 4 + 1] + redq[row * 4 + 2] +
                      redq[row * 4 + 3];
            inv[mi][half] = 1.f / fmaxf(sqrtf(t), 1e-12f);
        }

    if (LAYER == 1) {
#pragma unroll
        for (int mi = 0; mi < 2; mi++)
#pragma unroll
            for (int half = 0; half < 2; half++) {
                int row = warpM * 32 + mi * 16 + quad + half * 8;
                int gm = m0 + row;
                if (gm < N_NODES) {
#pragma unroll
                    for (int nj = 0; nj < NFRAG; nj++) {
                        float2 o;
                        o.x = acc[mi][nj][half * 2] * inv[mi][half];
                        o.y = acc[mi][nj][half * 2 + 1] * inv[mi][half];
                        *(float2*)(dst + (size_t)gm * N_OUT + warpN * WN + nj * 8 +
                                   qt * 2) = o;
                    }
                }
            }
    } else {
        float* redm = (float*)(sm + OFF_RED + 1024);
        float* reds = (float*)(sm + OFF_RED + 2048);
#pragma unroll
        for (int mi = 0; mi < 2; mi++)
#pragma unroll
            for (int half = 0; half < 2; half++) {
                float mx = -1e30f;
#pragma unroll
                for (int nj = 0; nj < NFRAG; nj++) {
                    float z0 = acc[mi][nj][half * 2] * inv[mi][half];
                    float z1 = acc[mi][nj][half * 2 + 1] * inv[mi][half];
                    acc[mi][nj][half * 2] = z0;
                    acc[mi][nj][half * 2 + 1] = z1;
                    mx = fmaxf(mx, fmaxf(z0, z1));
                }
                mx = fmaxf(mx, __shfl_xor_sync(0xffffffffu, mx, 1));
                mx = fmaxf(mx, __shfl_xor_sync(0xffffffffu, mx, 2));
                int row = warpM * 32 + mi * 16 + quad + half * 8;
                if (qt == 0) redm[row * 4 + warpN] = mx;
            }
        __syncthreads();
        float mxr[2][2];
#pragma unroll
        for (int mi = 0; mi < 2; mi++)
#pragma unroll
            for (int half = 0; half < 2; half++) {
                int row = warpM * 32 + mi * 16 + quad + half * 8;
                mxr[mi][half] = fmaxf(fmaxf(redm[row * 4], redm[row * 4 + 1]),
                                      fmaxf(redm[row * 4 + 2], redm[row * 4 + 3]));
            }
#pragma unroll
        for (int mi = 0; mi < 2; mi++)
#pragma unroll
            for (int half = 0; half < 2; half++) {
                float se = 0.f;
#pragma unroll
                for (int nj = 0; nj < NFRAG; nj++) {
                    se += __expf(acc[mi][nj][half * 2] - mxr[mi][half]);
                    se += __expf(acc[mi][nj][half * 2 + 1] - mxr[mi][half]);
                }
                se += __shfl_xor_sync(0xffffffffu, se, 1);
                se += __shfl_xor_sync(0xffffffffu, se, 2);
                int row = warpM * 32 + mi * 16 + quad + half * 8;
                if (qt == 0) reds[row * 4 + warpN] = se;
            }
        __syncthreads();
#pragma unroll
        for (int mi = 0; mi < 2; mi++)
#pragma unroll
            for (int half = 0; half < 2; half++) {
                int row = warpM * 32 + mi * 16 + quad + half * 8;
                float se = reds[row * 4] + reds[row * 4 + 1] + reds[row * 4 + 2] +
                           reds[row * 4 + 3];
                float lse = mxr[mi][half] + __logf(se);
                int gm = m0 + row;
                if (gm < N_NODES) {
#pragma unroll
                    for (int nj = 0; nj < NFRAG; nj++) {
                        float2 o;
                        o.x = acc[mi][nj][half * 2] - lse;
                        o.y = acc[mi][nj][half * 2 + 1] - lse;
                        *(float2*)(dst + (size_t)gm * N_OUT + warpN * WN + nj * 8 +
                                   qt * 2) = o;
                    }
                }
            }
    }
}

// ---------------- launch -----------------
extern "C" void kernel_launch(void* const* d_in, const int* in_sizes, int n_in,
                              void* d_out, int out_size) {
    const float* x   = (const float*)d_in[0];
    const int*   ei  = (const int*)d_in[1];
    const float* W1l = (const float*)d_in[2];
    const float* W1r = (const float*)d_in[3];
    const float* b1  = (const float*)d_in[4];
    const float* W2l = (const float*)d_in[5];
    const float* W2r = (const float*)d_in[6];
    const float* b2  = (const float*)d_in[7];
    float* out = (float*)d_out;

    const int* src = ei;            // edge_index[0]
    const int* dst = ei + N_EDGES;  // edge_index[1]

    // weight prep (bf16 split + transpose)
    k_prep_w<<<384, 256>>>(W1l, W1r, W2l, W2r);

    // CSR by destination (3-phase coalesced scan)
    k_zero_deg<<<SCAN_BLOCKS, 256>>>();
    k_count<<<592, 256>>>(dst);
    k_scan1<<<SCAN_BLOCKS, 256>>>();
    k_scan2<<<1, 256>>>();
    k_scan3<<<SCAN_BLOCKS, 256>>>();
    k_fill<<<592, 256>>>(src, dst);

    const int gblocks = (N_NODES + 63) / 64;   // 782

    // layer 1
    k_agg<false><<<(N_NODES + 7) / 8, 256>>>(x);
    k_mma<1><<<gblocks, 256>>>(x, b1, out);

    // layer 2
    k_agg<true><<<(N_NODES + 7) / 8, 256>>>(x);
    k_mma<2><<<gblocks, 256>>>(x, b2, out);
}